// round 1
// baseline (speedup 1.0000x reference)
#include <cuda_runtime.h>
#include <math.h>

// ---------------- scratch (static device globals; no allocation) ----------------
#define BMAX 4096
__device__ float d_h1[BMAX * 8 * 16 * 16];   // after conv1+pool
__device__ float d_h2[BMAX * 16 * 8 * 8];    // after conv2+pool
__device__ float d_feats[BMAX * 32];
__device__ float d_g[BMAX * 16];
__device__ float d_q[BMAX * 16];
__device__ float d_k[BMAX * 16];
__device__ float d_attn[BMAX * 16];
__device__ float d_outpre[BMAX * 2];
__device__ float d_ab[4];                    // bn scale/shift: A0,A1,B0,B1

// ---------------- conv1 (1->8, 32x32, SAME) + relu + maxpool2 -> 8x16x16 ----------------
__global__ void __launch_bounds__(256) k_conv1(const float* __restrict__ x,
                                               const float* __restrict__ w,
                                               const float* __restrict__ bias) {
    __shared__ float img[1024];   // 32x32
    __shared__ float ws[72];      // 8x1x3x3
    __shared__ float bs[8];
    int b = blockIdx.x, t = threadIdx.x;
    for (int i = t; i < 1024; i += 256) img[i] = x[b * 1024 + i];
    if (t < 72) ws[t] = w[t];
    if (t < 8) bs[t] = bias[t];
    __syncthreads();

    // idx = c*256 + ph*16 + pw ; stride 256 keeps (ph,pw) fixed, c varies -> reuse patch
    int rem = t;            // t in [0,256): ph,pw for this thread
    int ph = rem >> 4, pw = rem & 15;
    // load 4x4 input patch once (zero padded)
    float p[4][4];
#pragma unroll
    for (int yy = 0; yy < 4; yy++) {
        int iy = 2 * ph - 1 + yy;
#pragma unroll
        for (int xx = 0; xx < 4; xx++) {
            int ix = 2 * pw - 1 + xx;
            p[yy][xx] = ((unsigned)iy < 32u && (unsigned)ix < 32u) ? img[iy * 32 + ix] : 0.f;
        }
    }
#pragma unroll
    for (int c = 0; c < 8; c++) {
        float a00 = bs[c], a01 = bs[c], a10 = bs[c], a11 = bs[c];
#pragma unroll
        for (int ky = 0; ky < 3; ky++)
#pragma unroll
            for (int kx = 0; kx < 3; kx++) {
                float wv = ws[c * 9 + ky * 3 + kx];
                a00 += p[ky][kx] * wv;
                a01 += p[ky][kx + 1] * wv;
                a10 += p[ky + 1][kx] * wv;
                a11 += p[ky + 1][kx + 1] * wv;
            }
        float m = fmaxf(fmaxf(a00, a01), fmaxf(a10, a11));
        m = fmaxf(m, 0.f);   // relu commutes with max
        d_h1[b * 2048 + c * 256 + rem] = m;
    }
}

// ---------------- conv2 (8->16, 16x16, SAME) + relu + maxpool2 -> 16x8x8 ----------------
__global__ void __launch_bounds__(256) k_conv2(const float* __restrict__ w,
                                               const float* __restrict__ bias) {
    __shared__ float img[2048];   // 8x16x16
    __shared__ float ws[1152];    // 16x8x3x3
    __shared__ float bs[16];
    int b = blockIdx.x, t = threadIdx.x;
    for (int i = t; i < 2048; i += 256) img[i] = d_h1[b * 2048 + i];
    for (int i = t; i < 1152; i += 256) ws[i] = w[i];
    if (t < 16) bs[t] = bias[t];
    __syncthreads();

    // 1024 pooled outputs, stride 256: rem fixed, oc in {c0, c0+4, c0+8, c0+12}
    int c0 = t >> 6;            // 0..3
    int rem = t & 63;
    int ph = rem >> 3, pw = rem & 7;
    float acc[4][4];            // [which oc][2x2 window flattened]
#pragma unroll
    for (int oo = 0; oo < 4; oo++) {
        float bv = bs[c0 + 4 * oo];
#pragma unroll
        for (int z = 0; z < 4; z++) acc[oo][z] = bv;
    }
    for (int ic = 0; ic < 8; ic++) {
        // load patch once per ic
        float p[4][4];
        const float* ip = img + ic * 256;
#pragma unroll
        for (int yy = 0; yy < 4; yy++) {
            int iy = 2 * ph - 1 + yy;
#pragma unroll
            for (int xx = 0; xx < 4; xx++) {
                int ix = 2 * pw - 1 + xx;
                p[yy][xx] = ((unsigned)iy < 16u && (unsigned)ix < 16u) ? ip[iy * 16 + ix] : 0.f;
            }
        }
#pragma unroll
        for (int oo = 0; oo < 4; oo++) {
            const float* wp = ws + (c0 + 4 * oo) * 72 + ic * 9;
#pragma unroll
            for (int ky = 0; ky < 3; ky++)
#pragma unroll
                for (int kx = 0; kx < 3; kx++) {
                    float wv = wp[ky * 3 + kx];
                    acc[oo][0] += p[ky][kx] * wv;
                    acc[oo][1] += p[ky][kx + 1] * wv;
                    acc[oo][2] += p[ky + 1][kx] * wv;
                    acc[oo][3] += p[ky + 1][kx + 1] * wv;
                }
        }
    }
#pragma unroll
    for (int oo = 0; oo < 4; oo++) {
        float m = fmaxf(fmaxf(acc[oo][0], acc[oo][1]), fmaxf(acc[oo][2], acc[oo][3]));
        m = fmaxf(m, 0.f);
        d_h2[b * 1024 + (c0 + 4 * oo) * 64 + rem] = m;
    }
}

// ---------------- conv3 (16->32, 8x8, SAME) + relu + spatial mean -> feats (32) ----------------
__global__ void __launch_bounds__(256) k_conv3(const float* __restrict__ w,
                                               const float* __restrict__ bias) {
    __shared__ float img[1024];   // 16x8x8
    __shared__ float ws[4608];    // 32x16x3x3
    __shared__ float bs[32];
    int b = blockIdx.x, t = threadIdx.x;
    for (int i = t; i < 1024; i += 256) img[i] = d_h2[b * 1024 + i];
    for (int i = t; i < 4608; i += 256) ws[i] = w[i];
    if (t < 32) bs[t] = bias[t];
    __syncthreads();

    int c = t >> 3;        // output channel (0..31)
    int oy = t & 7;        // this thread handles one full output row (8 cols)
    float acc[8];
#pragma unroll
    for (int ox = 0; ox < 8; ox++) acc[ox] = bs[c];

    for (int ic = 0; ic < 16; ic++) {
        const float* ip = img + ic * 64;
        float p[3][10];    // rows oy-1..oy+1, cols -1..8 (zero padded)
#pragma unroll
        for (int ky = 0; ky < 3; ky++) {
            int iy = oy - 1 + ky;
            bool rowok = ((unsigned)iy < 8u);
#pragma unroll
            for (int xx = 0; xx < 10; xx++) {
                int ix = xx - 1;
                p[ky][xx] = (rowok && (unsigned)ix < 8u) ? ip[iy * 8 + ix] : 0.f;
            }
        }
        const float* wp = ws + c * 144 + ic * 9;
        float wv[9];
#pragma unroll
        for (int z = 0; z < 9; z++) wv[z] = wp[z];
#pragma unroll
        for (int ox = 0; ox < 8; ox++)
#pragma unroll
            for (int ky = 0; ky < 3; ky++)
#pragma unroll
                for (int kx = 0; kx < 3; kx++)
                    acc[ox] += p[ky][ox + kx] * wv[ky * 3 + kx];
    }
    float partial = 0.f;
#pragma unroll
    for (int ox = 0; ox < 8; ox++) partial += fmaxf(acc[ox], 0.f);
    // reduce 8 rows (consecutive lanes share c)
    int sub = t & 7;
#pragma unroll
    for (int off = 4; off; off >>= 1) {
        float o = __shfl_down_sync(0xffffffffu, partial, off, 8);
        if (sub + off < 8) partial += o;
    }
    if (sub == 0) d_feats[b * 32 + c] = partial * (1.f / 64.f);
}

// ---------------- GNN: a=tanh(f W1^T), g=tanh(a W2^T), q/k via 4x4 rotation ----------------
__global__ void __launch_bounds__(256) k_gnn(const float* __restrict__ w1,
                                             const float* __restrict__ w2,
                                             const float* __restrict__ R, int B) {
    __shared__ float fs[8][32];
    __shared__ float as[8][32];
    __shared__ float gs[8][16];
    int t = threadIdx.x, wrp = t >> 5, lane = t & 31;
    int row = blockIdx.x * 8 + wrp;
    if (row >= B) return;
    fs[wrp][lane] = d_feats[row * 32 + lane];
    __syncwarp();
    float a = 0.f;
#pragma unroll
    for (int i = 0; i < 32; i++) a += fs[wrp][i] * w1[lane * 32 + i];
    as[wrp][lane] = tanhf(a);
    __syncwarp();
    if (lane < 16) {
        float gg = 0.f;
#pragma unroll
        for (int i = 0; i < 32; i++) gg += as[wrp][i] * w2[lane * 32 + i];
        gg = tanhf(gg);
        gs[wrp][lane] = gg;
        d_g[row * 16 + lane] = gg;
    }
    __syncwarp();
    if (lane < 16) {
        int r = lane >> 2, cc = lane & 3;
        float qv = 0.f, kv = 0.f;
#pragma unroll
        for (int m = 0; m < 4; m++) {
            float gm = gs[wrp][r * 4 + m];
            qv += gm * R[m * 4 + cc];   // g @ R
            kv += gm * R[cc * 4 + m];   // g @ R^T
        }
        d_q[row * 16 + lane] = qv;
        d_k[row * 16 + lane] = kv;
    }
}

// ---------------- attention: softmax(q k^T * scale) @ g, flash-style ----------------
// 32 rows/block, 8 threads/row; k/g tiles of 256 rows staged in smem.
__global__ void __launch_bounds__(256) k_attn(const float* __restrict__ ent, int B) {
    __shared__ float kt[256 * 16];
    __shared__ float gt[256 * 16];
    int t = threadIdx.x;
    int r = t >> 3, part = t & 7;
    int row = blockIdx.x * 32 + r;
    float scale = (cosf(ent[0]) + cosf(ent[1]) + cosf(ent[2])) * (1.f / 3.f) * 0.25f;

    float q[16];
#pragma unroll
    for (int d = 0; d < 16; d++) q[d] = d_q[row * 16 + d];
    float m = -INFINITY, s = 0.f, acc[16];
#pragma unroll
    for (int d = 0; d < 16; d++) acc[d] = 0.f;

    int ntiles = (B + 255) >> 8;
    for (int jt = 0; jt < ntiles; jt++) {
        int base = jt << 8;
        int cnt = min(256, B - base);
        __syncthreads();
        for (int i = t; i < cnt * 16; i += 256) {
            kt[i] = d_k[base * 16 + i];
            gt[i] = d_g[base * 16 + i];
        }
        __syncthreads();
        for (int jj = part; jj < cnt; jj += 8) {
            const float* kp = kt + jj * 16;
            float dot = 0.f;
#pragma unroll
            for (int d = 0; d < 16; d++) dot += q[d] * kp[d];
            float sv = dot * scale;
            float mn = fmaxf(m, sv);
            float corr = __expf(m - mn);
            float pe = __expf(sv - mn);
            s = s * corr + pe;
            const float* gp = gt + jj * 16;
#pragma unroll
            for (int d = 0; d < 16; d++) acc[d] = acc[d] * corr + pe * gp[d];
            m = mn;
        }
    }
    // merge 8 partial softmax states (consecutive lanes, width-8 shuffles)
#pragma unroll
    for (int off = 4; off; off >>= 1) {
        float m2 = __shfl_down_sync(0xffffffffu, m, off, 8);
        float s2 = __shfl_down_sync(0xffffffffu, s, off, 8);
        float mn = fmaxf(m, m2);
        float c1 = __expf(m - mn), c2 = __expf(m2 - mn);
        float snew = s * c1 + s2 * c2;
#pragma unroll
        for (int d = 0; d < 16; d++) {
            float a2 = __shfl_down_sync(0xffffffffu, acc[d], off, 8);
            float anew = acc[d] * c1 + a2 * c2;
            if (part + off < 8) acc[d] = anew;
        }
        if (part + off < 8) { s = snew; m = mn; }
    }
    if (part == 0) {
        float inv = 1.f / s;
#pragma unroll
        for (int d = 0; d < 16; d++) d_attn[row * 16 + d] = acc[d] * inv;
    }
}

// ---------------- head: [g,attn] @ reduce_w^T + rb  -> @ cls_w^T + cb ----------------
__global__ void __launch_bounds__(256) k_head(const float* __restrict__ rw,
                                              const float* __restrict__ rb,
                                              const float* __restrict__ cw,
                                              const float* __restrict__ cb, int B) {
    int i = blockIdx.x * 256 + threadIdx.x;
    if (i >= B) return;
    float r0 = rb[0], r1 = rb[1];
#pragma unroll
    for (int d = 0; d < 16; d++) {
        float gv = d_g[i * 16 + d];
        float av = d_attn[i * 16 + d];
        r0 += gv * rw[d] + av * rw[16 + d];
        r1 += gv * rw[32 + d] + av * rw[48 + d];
    }
    // fraud layers are identity (all params zero)
    d_outpre[i * 2 + 0] = cb[0] + r0 * cw[0] + r1 * cw[1];
    d_outpre[i * 2 + 1] = cb[1] + r0 * cw[2] + r1 * cw[3];
}

// ---------------- batch-norm stats (1 block, deterministic tree reduction) ----------------
__global__ void __launch_bounds__(256) k_stats(const float* __restrict__ gamma,
                                               const float* __restrict__ beta, int B) {
    __shared__ float sh[1024];
    int t = threadIdx.x;
    float s0 = 0.f, s1 = 0.f, q0 = 0.f, q1 = 0.f;
    for (int i = t; i < B; i += 256) {
        float a = d_outpre[i * 2], b2 = d_outpre[i * 2 + 1];
        s0 += a; q0 += a * a; s1 += b2; q1 += b2 * b2;
    }
    sh[t] = s0; sh[256 + t] = s1; sh[512 + t] = q0; sh[768 + t] = q1;
    __syncthreads();
    for (int off = 128; off; off >>= 1) {
        if (t < off) {
            sh[t] += sh[t + off];
            sh[256 + t] += sh[256 + t + off];
            sh[512 + t] += sh[512 + t + off];
            sh[768 + t] += sh[768 + t + off];
        }
        __syncthreads();
    }
    if (t == 0) {
        float invB = 1.f / (float)B;
        float mu0 = sh[0] * invB, mu1 = sh[256] * invB;
        float v0 = sh[512] * invB - mu0 * mu0;
        float v1 = sh[768] * invB - mu1 * mu1;
        float A0 = gamma[0] * rsqrtf(v0 + 1e-5f);
        float A1 = gamma[1] * rsqrtf(v1 + 1e-5f);
        d_ab[0] = A0; d_ab[1] = A1;
        d_ab[2] = beta[0] - mu0 * A0;
        d_ab[3] = beta[1] - mu1 * A1;
    }
}

__global__ void __launch_bounds__(256) k_norm(float* __restrict__ out, int B) {
    int i = blockIdx.x * 256 + threadIdx.x;
    if (i >= B) return;
    out[i * 2 + 0] = d_outpre[i * 2 + 0] * d_ab[0] + d_ab[2];
    out[i * 2 + 1] = d_outpre[i * 2 + 1] * d_ab[1] + d_ab[3];
}

// ---------------- launch ----------------
extern "C" void kernel_launch(void* const* d_in, const int* in_sizes, int n_in,
                              void* d_out, int out_size) {
    const float* x   = (const float*)d_in[0];
    const float* c1w = (const float*)d_in[1];
    const float* c1b = (const float*)d_in[2];
    const float* c2w = (const float*)d_in[3];
    const float* c2b = (const float*)d_in[4];
    const float* c3w = (const float*)d_in[5];
    const float* c3b = (const float*)d_in[6];
    const float* g1  = (const float*)d_in[7];
    const float* g2  = (const float*)d_in[8];
    const float* rot = (const float*)d_in[9];
    const float* ent = (const float*)d_in[10];
    const float* rw  = (const float*)d_in[11];
    const float* rb  = (const float*)d_in[12];
    const float* cw  = (const float*)d_in[13];
    const float* cb  = (const float*)d_in[14];
    const float* gam = (const float*)d_in[15];
    const float* bet = (const float*)d_in[16];

    int B = in_sizes[0] / 1024;   // x is (B,1,32,32)

    k_conv1<<<B, 256>>>(x, c1w, c1b);
    k_conv2<<<B, 256>>>(c2w, c2b);
    k_conv3<<<B, 256>>>(c3w, c3b);
    k_gnn<<<(B + 7) / 8, 256>>>(g1, g2, rot, B);
    k_attn<<<B / 32, 256>>>(ent, B);
    k_head<<<(B + 255) / 256, 256>>>(rw, rb, cw, cb, B);
    k_stats<<<1, 256>>>(gam, bet, B);
    k_norm<<<(B + 255) / 256, 256>>>((float*)d_out, B);
}